// round 7
// baseline (speedup 1.0000x reference)
#include <cuda_runtime.h>
#include <cuda_bf16.h>
#include <mma.h>
#include <math.h>
#include <stdint.h>

#define B_   512
#define L_   512
#define KK_  10

using namespace nvcuda;

// ---------------- scratch (device globals; no allocations) ----------------
__device__ uint32_t g_h1[B_ * L_ * 56];          // h1 bf16x2 [b][l][112ch]
__device__ uint32_t g_h2[B_ * L_ * 56];
__device__ float    g_logits[B_ * L_];
__device__ float    g_hmean[B_ * 128];
__device__ float    g_gz[B_ * 128];
__device__ __nv_bfloat16 g_Wb1[3 * 128 * 120];   // [tap][f pad128][k pad120]
__device__ __nv_bfloat16 g_Wb2[3 * 128 * 120];
__device__ __nv_bfloat16 g_WbL[3 * 128 * 120];
__device__ __nv_bfloat16 g_Wb3[128 * 136];       // conv3 loc half, stride 136

// ---------------- K0: weight prep -> padded bf16 blobs ---------------------
__global__ void k0_prep(const float* __restrict__ w1, const float* __restrict__ w2,
                        const float* __restrict__ wl, const float* __restrict__ w3) {
    int id = blockIdx.x * 256 + threadIdx.x;
    if (id >= 155648) return;
    if (id < 138240) {
        int conv = id / 46080, rem = id - conv * 46080;
        int t = rem / 15360, p = rem - t * 15360;
        int f = p / 120, k = p - f * 120;
        float v = 0.f;
        const float* src = (conv == 0) ? w1 : (conv == 1) ? w2 : wl;
        if (f < 100 && k < 100) v = src[f * 300 + k * 3 + t];
        __nv_bfloat16* dst = (conv == 0) ? g_Wb1 : (conv == 1) ? g_Wb2 : g_WbL;
        dst[t * 15360 + f * 120 + k] = __float2bfloat16(v);
    } else {
        int p = id - 138240;
        int f = p / 136, j = p - f * 136;
        float v = 0.f;
        if (f < 100 && j < 100) v = w3[f * 200 + 100 + j];
        g_Wb3[f * 136 + j] = __float2bfloat16(v);
    }
}

__device__ __forceinline__ uint32_t smem_u32(const void* p) {
    uint32_t a;
    asm("{ .reg .u64 t; cvta.to.shared.u64 t, %1; cvt.u32.u64 %0, t; }" : "=r"(a) : "l"(p));
    return a;
}

// ---------------- conv GEMM cores (all weights resident, no syncs) ---------
// C[f][l] = sum_{t,k} W[t][f][k] * sData[(l+t)][k]; warps 2(f) x 4(l), 64f x 32l.
__device__ __forceinline__ void conv_mma3(
    const __nv_bfloat16* sData, const __nv_bfloat16* sW,
    wmma::fragment<wmma::accumulator, 16, 16, 16, float> (&c)[4][2], int tid) {
    const int wid = tid >> 5, wf = wid >> 2, wl = wid & 3;
#pragma unroll
    for (int i = 0; i < 4; i++)
#pragma unroll
        for (int j = 0; j < 2; j++) wmma::fill_fragment(c[i][j], 0.f);
#pragma unroll
    for (int t = 0; t < 3; t++) {
#pragma unroll
        for (int ks = 0; ks < 7; ks++) {
            wmma::fragment<wmma::matrix_b, 16, 16, 16, __nv_bfloat16, wmma::col_major> bf[2];
#pragma unroll
            for (int j = 0; j < 2; j++)
                wmma::load_matrix_sync(bf[j], sData + ks * 16 + (wl * 32 + j * 16 + t) * 120, 120);
#pragma unroll
            for (int i = 0; i < 4; i++) {
                wmma::fragment<wmma::matrix_a, 16, 16, 16, __nv_bfloat16, wmma::row_major> af;
                wmma::load_matrix_sync(af, sW + t * 15360 + (wf * 64 + i * 16) * 120 + ks * 16, 120);
#pragma unroll
                for (int j = 0; j < 2; j++) wmma::mma_sync(c[i][j], af, bf[j], c[i][j]);
            }
        }
    }
}
// 1x1 conv (conv3): K=128 slices over Loc, A stride 136.
__device__ __forceinline__ void conv_mma1(
    const __nv_bfloat16* sData, const __nv_bfloat16* sW3,
    wmma::fragment<wmma::accumulator, 16, 16, 16, float> (&c)[4][2], int tid) {
    const int wid = tid >> 5, wf = wid >> 2, wl = wid & 3;
#pragma unroll
    for (int i = 0; i < 4; i++)
#pragma unroll
        for (int j = 0; j < 2; j++) wmma::fill_fragment(c[i][j], 0.f);
#pragma unroll
    for (int ks = 0; ks < 8; ks++) {
        wmma::fragment<wmma::matrix_b, 16, 16, 16, __nv_bfloat16, wmma::col_major> bf[2];
#pragma unroll
        for (int j = 0; j < 2; j++)
            wmma::load_matrix_sync(bf[j], sData + ks * 16 + (wl * 32 + j * 16) * 120, 120);
#pragma unroll
        for (int i = 0; i < 4; i++) {
            wmma::fragment<wmma::matrix_a, 16, 16, 16, __nv_bfloat16, wmma::row_major> af;
            wmma::load_matrix_sync(af, sW3 + (wf * 64 + i * 16) * 136 + ks * 16, 136);
#pragma unroll
            for (int j = 0; j < 2; j++) wmma::mma_sync(c[i][j], af, bf[j], c[i][j]);
        }
    }
}

// ---------------- KC1: emb gather + conv1 -> h1 + hmean --------------------
// smem: data[134][120]bf16 @0 (32160) | sW 3 taps @32160 (92160) | C 64x132 f32
// @124320 (33792) | bias @158112 (512)  => 158624 B
#define C1_W    32160
#define C1_C    124320
#define C1_BIAS 158112
#define C1_SMEM 158624
__global__ __launch_bounds__(256) void kC1(const int* __restrict__ x,
                                           const float* __restrict__ emb,
                                           const float* __restrict__ b1) {
    extern __shared__ char sm[];
    __nv_bfloat16* sData = (__nv_bfloat16*)sm;
    uint32_t* sD32 = (uint32_t*)sm;
    __nv_bfloat16* sW = (__nv_bfloat16*)(sm + C1_W);
    float* sC2 = (float*)(sm + C1_C);
    float* sBias = (float*)(sm + C1_BIAS);
    const int b = blockIdx.x, tid = threadIdx.x;
    const int* xb = x + b * L_;
    const int wid = tid >> 5, wf = wid >> 2, wl = wid & 3;

    for (int idx = tid; idx < 5760; idx += 256)
        ((uint4*)sW)[idx] = ((const uint4*)g_Wb1)[idx];
    for (int idx = tid; idx < 240; idx += 256) sD32[130 * 60 + idx] = 0;  // halo rows 130-133
    if (tid < 128) sBias[tid] = (tid < 100) ? b1[tid] : 0.f;

    float msum = 0.f;
    for (int c = 0; c < 4; c++) {
        const int l0 = c * 128;
        __syncthreads();                         // data region free
        for (int idx = tid; idx < 130 * 60; idx += 256) {
            int r = idx / 60, cpr = idx - r * 60;
            int l = l0 - 1 + r;
            uint32_t pk = 0;
            if ((unsigned)l < (unsigned)L_ && cpr < 50) {
                int tok = xb[l];
                float v0 = emb[tok * 100 + 2 * cpr];
                float v1 = emb[tok * 100 + 2 * cpr + 1];
                __nv_bfloat162 bp = __floats2bfloat162_rn(v0, v1);
                pk = *reinterpret_cast<uint32_t*>(&bp);
            }
            sD32[r * 60 + cpr] = pk;
        }
        __syncthreads();

        wmma::fragment<wmma::accumulator, 16, 16, 16, float> cf[4][2];
        conv_mma3(sData, sW, cf, tid);

#pragma unroll
        for (int p = 0; p < 2; p++) {
            if ((wl >> 1) == p) {
#pragma unroll
                for (int i = 0; i < 4; i++)
#pragma unroll
                    for (int j = 0; j < 2; j++)
                        wmma::store_matrix_sync(sC2 + (wf * 64 + i * 16) + ((wl & 1) * 32 + j * 16) * 132,
                                                cf[i][j], 132, wmma::mem_col_major);
            }
            __syncthreads();
            if (tid < 128) {
                int lr = tid >> 1, half = tid & 1;
                const float* cr = sC2 + lr * 132 + half * 56;
                const float* bb = sBias + half * 56;
                uint32_t pk[28];
#pragma unroll
                for (int q = 0; q < 28; q++) {
                    float v0 = fmaxf(cr[2 * q] + bb[2 * q], 0.f);
                    float v1 = fmaxf(cr[2 * q + 1] + bb[2 * q + 1], 0.f);
                    __nv_bfloat162 bp = __floats2bfloat162_rn(v0, v1);
                    pk[q] = *reinterpret_cast<uint32_t*>(&bp);
                }
                uint4* d4 = (uint4*)(g_h1 + ((size_t)b * L_ + l0 + p * 64 + lr) * 56 + half * 28);
#pragma unroll
                for (int q = 0; q < 7; q++)
                    d4[q] = make_uint4(pk[4 * q], pk[4 * q + 1], pk[4 * q + 2], pk[4 * q + 3]);
                float bf_ = sBias[tid], s = 0.f;
                for (int l = 0; l < 64; l++) s += fmaxf(sC2[tid + l * 132] + bf_, 0.f);
                msum += s;
            }
            __syncthreads();
        }
    }
    if (tid < 128) g_hmean[b * 128 + tid] = msum * (1.f / (float)L_);
}

// ---------------- KG: hmean -> g -> gz -------------------------------------
__global__ __launch_bounds__(128) void kG(const float* __restrict__ giw,
                                          const float* __restrict__ gib,
                                          const float* __restrict__ c3w,
                                          const float* __restrict__ c3b) {
    const int b = blockIdx.x, tid = threadIdx.x;
    __shared__ float shm[100], sg[100];
    if (tid < 100) shm[tid] = g_hmean[b * 128 + tid];
    __syncthreads();
    if (tid < 100) {
        float a = gib[tid];
        const float* wr = &giw[tid * 100];
        for (int f = 0; f < 100; f++) a = fmaf(wr[f], shm[f], a);
        sg[tid] = fmaxf(a, 0.f);
    }
    __syncthreads();
    if (tid < 100) {
        float a = c3b[tid];
        const float* wr = &c3w[tid * 200];
        for (int h = 0; h < 100; h++) a = fmaf(wr[h], sg[h], a);
        g_gz[b * 128 + tid] = a;
    }
}

// ---------------- KC2: conv2 (h1 -> h2), cp.async double-buffered ----------
// smem: data0 @0 (32160) | data1 @32160 | sW @64320 (92160) | C @156480 (33792)
// | bias @190272 (512) => 190784 B
#define C2_D1   32160
#define C2_W    64320
#define C2_C    156480
#define C2_BIAS 190272
#define C2_SMEM 190784
__device__ __forceinline__ void kc2_prefetch(uint32_t dst_u32, const uint4* src,
                                             int l0, int tid) {
    for (int idx = tid; idx < 130 * 15; idx += 256) {
        int r = idx / 15, q = idx - r * 15;
        int l = l0 - 1 + r;
        bool ok = (q < 14) && ((unsigned)l < (unsigned)L_);
        uint32_t d = dst_u32 + idx * 16;
        const void* s = ok ? (const void*)(src + (size_t)l * 14 + q) : (const void*)src;
        int sb = ok ? 16 : 0;
        asm volatile("cp.async.cg.shared.global [%0], [%1], 16, %2;" :: "r"(d), "l"(s), "r"(sb));
    }
    asm volatile("cp.async.commit_group;" ::: "memory");
}
__global__ __launch_bounds__(256) void kC2(const float* __restrict__ b2) {
    extern __shared__ char sm[];
    __nv_bfloat16* sW = (__nv_bfloat16*)(sm + C2_W);
    float* sC2 = (float*)(sm + C2_C);
    float* sBias = (float*)(sm + C2_BIAS);
    const int b = blockIdx.x, tid = threadIdx.x;
    const int wid = tid >> 5, wf = wid >> 2, wl = wid & 3;
    const uint4* src = (const uint4*)(g_h1 + (size_t)b * L_ * 56);
    const uint32_t base_u = smem_u32(sm);

    for (int idx = tid; idx < 5760; idx += 256)
        ((uint4*)sW)[idx] = ((const uint4*)g_Wb2)[idx];
    for (int idx = tid; idx < 120; idx += 256) {     // zero halo rows of both buffers
        int bs = idx / 60, k2 = idx - bs * 60;
        ((uint4*)(sm + bs * C2_D1))[130 * 15 + k2] = make_uint4(0, 0, 0, 0);
    }
    if (tid < 128) sBias[tid] = (tid < 100) ? b2[tid] : 0.f;
    kc2_prefetch(base_u, src, 0, tid);

    int cur = 0;
    for (int c = 0; c < 4; c++) {
        const int l0 = c * 128;
        asm volatile("cp.async.wait_group 0;" ::: "memory");
        __syncthreads();
        if (c < 3) kc2_prefetch(base_u + (cur ^ 1) * C2_D1, src, (c + 1) * 128, tid);

        wmma::fragment<wmma::accumulator, 16, 16, 16, float> cf[4][2];
        conv_mma3((const __nv_bfloat16*)(sm + cur * C2_D1), sW, cf, tid);

#pragma unroll
        for (int p = 0; p < 2; p++) {
            if ((wl >> 1) == p) {
#pragma unroll
                for (int i = 0; i < 4; i++)
#pragma unroll
                    for (int j = 0; j < 2; j++)
                        wmma::store_matrix_sync(sC2 + (wf * 64 + i * 16) + ((wl & 1) * 32 + j * 16) * 132,
                                                cf[i][j], 132, wmma::mem_col_major);
            }
            __syncthreads();
            if (tid < 128) {
                int lr = tid >> 1, half = tid & 1;
                const float* cr = sC2 + lr * 132 + half * 56;
                const float* bb = sBias + half * 56;
                uint32_t pk[28];
#pragma unroll
                for (int q = 0; q < 28; q++) {
                    float v0 = fmaxf(cr[2 * q] + bb[2 * q], 0.f);
                    float v1 = fmaxf(cr[2 * q + 1] + bb[2 * q + 1], 0.f);
                    __nv_bfloat162 bp = __floats2bfloat162_rn(v0, v1);
                    pk[q] = *reinterpret_cast<uint32_t*>(&bp);
                }
                uint4* d4 = (uint4*)(g_h2 + ((size_t)b * L_ + l0 + p * 64 + lr) * 56 + half * 28);
#pragma unroll
                for (int q = 0; q < 7; q++)
                    d4[q] = make_uint4(pk[4 * q], pk[4 * q + 1], pk[4 * q + 2], pk[4 * q + 3]);
            }
            __syncthreads();
        }
        cur ^= 1;
    }
}

// ---------------- KC3: li conv -> conv3(loc)+gz -> conv4 -> logits ---------
// smem: data @0 (32160) | sW @32160 (92160) | sW3 @124320 (34816) | C @159136
// (33792) | bias @192928 | gz @193440 | c4 @193952 => 194464 B
#define C3_W    32160
#define C3_W3   124320
#define C3_C    159136
#define C3_BIAS 192928
#define C3_GZ   193440
#define C3_C4   193952
#define C3_SMEM 194464
__global__ __launch_bounds__(256) void kC3(const float* __restrict__ lb,
                                           const float* __restrict__ c4w,
                                           const float* __restrict__ c4b) {
    extern __shared__ char sm[];
    __nv_bfloat16* sData = (__nv_bfloat16*)sm;
    uint32_t* sD32 = (uint32_t*)sm;
    __nv_bfloat16* sW = (__nv_bfloat16*)(sm + C3_W);
    __nv_bfloat16* sW3 = (__nv_bfloat16*)(sm + C3_W3);
    float* sC2 = (float*)(sm + C3_C);
    float* sBias = (float*)(sm + C3_BIAS);
    float* sGz = (float*)(sm + C3_GZ);
    float* sC4 = (float*)(sm + C3_C4);
    const int b = blockIdx.x, tid = threadIdx.x;
    const int wid = tid >> 5, wf = wid >> 2, wl = wid & 3;
    const uint4* src = (const uint4*)(g_h2 + (size_t)b * L_ * 56);
    const float c4bias = c4b[0];

    for (int idx = tid; idx < 5760; idx += 256)
        ((uint4*)sW)[idx] = ((const uint4*)g_WbL)[idx];
    for (int idx = tid; idx < 2176; idx += 256)
        ((uint4*)sW3)[idx] = ((const uint4*)g_Wb3)[idx];
    for (int idx = tid; idx < 60; idx += 256)
        ((uint4*)sm)[130 * 15 + idx] = make_uint4(0, 0, 0, 0);
    if (tid < 128) {
        sBias[tid] = (tid < 100) ? lb[tid] : 0.f;
        sGz[tid] = (tid < 100) ? g_gz[b * 128 + tid] : 0.f;
        sC4[tid] = (tid < 100) ? c4w[tid] : 0.f;
    }

    for (int c = 0; c < 4; c++) {
        const int l0 = c * 128;
        __syncthreads();
        for (int idx = tid; idx < 130 * 15; idx += 256) {
            int r = idx / 15, q = idx - r * 15;
            int l = l0 - 1 + r;
            uint4 v = make_uint4(0, 0, 0, 0);
            if (q < 14 && (unsigned)l < (unsigned)L_) v = src[l * 14 + q];
            ((uint4*)sm)[r * 15 + q] = v;
        }
        __syncthreads();

        wmma::fragment<wmma::accumulator, 16, 16, 16, float> cf[4][2];
        conv_mma3(sData, sW, cf, tid);

        // Loc = relu(C + lb) -> bf16 pairs back into sData rows 0..127
#pragma unroll
        for (int p = 0; p < 2; p++) {
            if ((wl >> 1) == p) {
#pragma unroll
                for (int i = 0; i < 4; i++)
#pragma unroll
                    for (int j = 0; j < 2; j++)
                        wmma::store_matrix_sync(sC2 + (wf * 64 + i * 16) + ((wl & 1) * 32 + j * 16) * 132,
                                                cf[i][j], 132, wmma::mem_col_major);
            }
            __syncthreads();
            if (tid < 128) {
                int lr = tid >> 1, half = tid & 1;
                const float* cr = sC2 + lr * 132 + half * 56;
                const float* bb = sBias + half * 56;
                uint32_t pk[28];
#pragma unroll
                for (int q = 0; q < 28; q++) {
                    float v0 = fmaxf(cr[2 * q] + bb[2 * q], 0.f);
                    float v1 = fmaxf(cr[2 * q + 1] + bb[2 * q + 1], 0.f);
                    __nv_bfloat162 bp = __floats2bfloat162_rn(v0, v1);
                    pk[q] = *reinterpret_cast<uint32_t*>(&bp);
                }
                uint4* d4 = (uint4*)(sD32 + (size_t)(p * 64 + lr) * 60 + half * 28);
#pragma unroll
                for (int q = 0; q < 7; q++)
                    d4[q] = make_uint4(pk[4 * q], pk[4 * q + 1], pk[4 * q + 2], pk[4 * q + 3]);
            }
            __syncthreads();
        }

        conv_mma1(sData, sW3, cf, tid);          // conv3 loc half (1x1)

#pragma unroll
        for (int p = 0; p < 2; p++) {
            if ((wl >> 1) == p) {
#pragma unroll
                for (int i = 0; i < 4; i++)
#pragma unroll
                    for (int j = 0; j < 2; j++)
                        wmma::store_matrix_sync(sC2 + (wf * 64 + i * 16) + ((wl & 1) * 32 + j * 16) * 132,
                                                cf[i][j], 132, wmma::mem_col_major);
            }
            __syncthreads();
            if (tid < 128) {
                int lr = tid >> 1, half = tid & 1;
                const float* cr = sC2 + lr * 132 + half * 64;
                const float* gz = sGz + half * 64;
                const float* c4 = sC4 + half * 64;
                float part = 0.f;
#pragma unroll 8
                for (int f = 0; f < 64; f++)
                    part += c4[f] * fmaxf(cr[f] + gz[f], 0.f);
                part += __shfl_xor_sync(0xffffffffu, part, 1);
                if (half == 0) g_logits[b * L_ + l0 + p * 64 + lr] = part + c4bias;
            }
            __syncthreads();
        }
    }
}

// ---------------- reductions -----------------------------------------------
__device__ __forceinline__ float bmax256(float v, float* sred) {
#pragma unroll
    for (int o = 16; o > 0; o >>= 1) v = fmaxf(v, __shfl_xor_sync(0xffffffffu, v, o));
    int w = threadIdx.x >> 5;
    if ((threadIdx.x & 31) == 0) sred[w] = v;
    __syncthreads();
    if (threadIdx.x == 0) {
        float t = sred[0];
#pragma unroll
        for (int i = 1; i < 8; i++) t = fmaxf(t, sred[i]);
        sred[0] = t;
    }
    __syncthreads();
    float r = sred[0];
    __syncthreads();
    return r;
}
__device__ __forceinline__ float bsum256(float v, float* sred) {
#pragma unroll
    for (int o = 16; o > 0; o >>= 1) v += __shfl_xor_sync(0xffffffffu, v, o);
    int w = threadIdx.x >> 5;
    if ((threadIdx.x & 31) == 0) sred[w] = v;
    __syncthreads();
    if (threadIdx.x == 0) {
        float t = sred[0];
#pragma unroll
        for (int i = 1; i < 8; i++) t += sred[i];
        sred[0] = t;
    }
    __syncthreads();
    float r = sred[0];
    __syncthreads();
    return r;
}

// ---------------- K4: gumbel softmax over L, max over K --------------------
__global__ __launch_bounds__(256) void k4_init(float* __restrict__ cs) {
    int i = blockIdx.x * 256 + threadIdx.x;
    if (i < B_ * L_) cs[i] = 0.f;
}
__global__ __launch_bounds__(256) void k4_gumbel(const float* __restrict__ u,
                                                 float* __restrict__ cs_out) {
    const int k = blockIdx.x, b = blockIdx.y, tid = threadIdx.x;
    __shared__ float sred[8];
    const float EPS = 1.1920929e-07f;
    const float invT = 1.0f / 0.3f;
    const float* lg = g_logits + b * L_;
    const float* ub = u + (b * KK_ + k) * L_;
    float u0 = ub[tid], u1 = ub[tid + 256];
    u0 = fminf(fmaxf(u0, EPS), 1.0f - EPS);
    u1 = fminf(fmaxf(u1, EPS), 1.0f - EPS);
    float nv0 = (-logf(-logf(u0)) + lg[tid]) * invT;
    float nv1 = (-logf(-logf(u1)) + lg[tid + 256]) * invT;
    float m = bmax256(fmaxf(nv0, nv1), sred);
    float e0 = expf(nv0 - m), e1 = expf(nv1 - m);
    float s = bsum256(e0 + e1, sred);
    float rs = 1.f / s;
    atomicMax((int*)&cs_out[b * L_ + tid], __float_as_int(e0 * rs));
    atomicMax((int*)&cs_out[b * L_ + tid + 256], __float_as_int(e1 * rs));
}

// ---------------- K5: weighted pooling + MLP + sigmoid ---------------------
__global__ __launch_bounds__(128) void k5_final(const int* __restrict__ x,
                                                const float* __restrict__ emb,
                                                const float* __restrict__ f1w,
                                                const float* __restrict__ f1b,
                                                const float* __restrict__ hw,
                                                const float* __restrict__ hb,
                                                const float* __restrict__ cs,
                                                float* __restrict__ out) {
    const int b = blockIdx.x, tid = threadIdx.x;
    __shared__ float scs[L_];
    __shared__ int sx[L_];
    __shared__ float spool[100];
    __shared__ float sh[100];
    __shared__ float sred[4];
    for (int l = tid; l < L_; l += 128) {
        scs[l] = cs[b * L_ + l];
        sx[l] = x[b * L_ + l];
    }
    __syncthreads();
    if (tid < 100) {
        float acc = 0.f;
        for (int l = 0; l < L_; l += 8) {
            float p[8];
#pragma unroll
            for (int q = 0; q < 8; q++) p[q] = emb[sx[l + q] * 100 + tid];
#pragma unroll
            for (int q = 0; q < 8; q++) acc = fmaf(scs[l + q], p[q], acc);
        }
        spool[tid] = acc * (1.f / (float)L_);
    }
    __syncthreads();
    if (tid < 100) {
        float a = f1b[tid];
        const float* wr = &f1w[tid * 100];
        for (int e = 0; e < 100; e++) a = fmaf(wr[e], spool[e], a);
        sh[tid] = fmaxf(a, 0.f);
    }
    __syncthreads();
    float hv = (tid < 100) ? hw[tid] * sh[tid] : 0.f;
#pragma unroll
    for (int o = 16; o > 0; o >>= 1) hv += __shfl_xor_sync(0xffffffffu, hv, o);
    if ((tid & 31) == 0) sred[tid >> 5] = hv;
    __syncthreads();
    if (tid == 0) {
        float t = sred[0] + sred[1] + sred[2] + sred[3] + hb[0];
        out[b] = 1.f / (1.f + expf(-t));
    }
}

// ---------------- launch ----------------------------------------------------
extern "C" void kernel_launch(void* const* d_in, const int* in_sizes, int n_in,
                              void* d_out, int out_size) {
    const int*   x   = (const int*)  d_in[0];
    const float* u   = (const float*)d_in[1];
    const float* emb = (const float*)d_in[2];
    const float* c1w = (const float*)d_in[3];
    const float* c1b = (const float*)d_in[4];
    const float* giw = (const float*)d_in[5];
    const float* gib = (const float*)d_in[6];
    const float* c2w = (const float*)d_in[7];
    const float* c2b = (const float*)d_in[8];
    const float* liw = (const float*)d_in[9];
    const float* lib = (const float*)d_in[10];
    const float* c3w = (const float*)d_in[11];
    const float* c3b = (const float*)d_in[12];
    const float* c4w = (const float*)d_in[13];
    const float* c4b = (const float*)d_in[14];
    const float* f1w = (const float*)d_in[15];
    const float* f1b = (const float*)d_in[16];
    const float* hw  = (const float*)d_in[17];
    const float* hb  = (const float*)d_in[18];

    float* out = (float*)d_out;          // [B,1] first
    float* cs  = out + B_;               // then csamples [B,L]

    cudaFuncSetAttribute(kC1, cudaFuncAttributeMaxDynamicSharedMemorySize, C1_SMEM);
    cudaFuncSetAttribute(kC2, cudaFuncAttributeMaxDynamicSharedMemorySize, C2_SMEM);
    cudaFuncSetAttribute(kC3, cudaFuncAttributeMaxDynamicSharedMemorySize, C3_SMEM);

    k0_prep<<<608, 256>>>(c1w, c2w, liw, c3w);
    kC1<<<B_, 256, C1_SMEM>>>(x, emb, c1b);
    kG<<<B_, 128>>>(giw, gib, c3w, c3b);
    kC2<<<B_, 256, C2_SMEM>>>(c2b);
    kC3<<<B_, 256, C3_SMEM>>>(lib, c4w, c4b);
    k4_init<<<(B_ * L_ + 255) / 256, 256>>>(cs);
    k4_gumbel<<<dim3(KK_, B_), 256>>>(u, cs);
    k5_final<<<B_, 128>>>(x, emb, f1w, f1b, hw, hb, cs, out);
}

// round 8
// speedup vs baseline: 1.3348x; 1.3348x over previous
#include <cuda_runtime.h>
#include <cuda_bf16.h>
#include <math.h>
#include <stdint.h>

#define B_   512
#define L_   512
#define KK_  10

// ---------------- scratch (device globals; no allocations) ----------------
__device__ uint32_t g_h1[B_ * L_ * 56];          // h1 bf16x2 [b][l][112ch]
__device__ uint32_t g_h2[B_ * L_ * 56];
__device__ float    g_logits[B_ * L_];
__device__ float    g_hpart[B_ * 4 * 128];
__device__ float    g_gz[B_ * 128];
__device__ __nv_bfloat16 g_Wb1[3 * 128 * 120];   // [tap][f pad128][k pad120]
__device__ __nv_bfloat16 g_Wb2[3 * 128 * 120];
__device__ __nv_bfloat16 g_WbL[3 * 128 * 120];
__device__ __nv_bfloat16 g_Wb3[112 * 120];       // conv3 loc half [f112][k120]

// ---------------- K0: weight prep -> padded bf16 blobs ---------------------
__global__ void k0_prep(const float* __restrict__ w1, const float* __restrict__ w2,
                        const float* __restrict__ wl, const float* __restrict__ w3) {
    int id = blockIdx.x * 256 + threadIdx.x;
    if (id >= 151680) return;
    if (id < 138240) {
        int conv = id / 46080, rem = id - conv * 46080;
        int t = rem / 15360, p = rem - t * 15360;
        int f = p / 120, k = p - f * 120;
        float v = 0.f;
        const float* src = (conv == 0) ? w1 : (conv == 1) ? w2 : wl;
        if (f < 100 && k < 100) v = src[f * 300 + k * 3 + t];
        __nv_bfloat16* dst = (conv == 0) ? g_Wb1 : (conv == 1) ? g_Wb2 : g_WbL;
        dst[t * 15360 + f * 120 + k] = __float2bfloat16(v);
    } else {
        int p = id - 138240;                     // < 13440
        int f = p / 120, k = p - f * 120;
        float v = 0.f;
        if (f < 100 && k < 100) v = w3[f * 200 + 100 + k];
        g_Wb3[p] = __float2bfloat16(v);
    }
}

// ---------------- PTX primitives -------------------------------------------
__device__ __forceinline__ uint32_t smem_u32(const void* p) {
    uint32_t a;
    asm("{ .reg .u64 t; cvta.to.shared.u64 t, %1; cvt.u32.u64 %0, t; }" : "=r"(a) : "l"(p));
    return a;
}
__device__ __forceinline__ void ldsm_x4(uint32_t& a0, uint32_t& a1, uint32_t& a2,
                                        uint32_t& a3, uint32_t addr) {
    asm volatile("ldmatrix.sync.aligned.m8n8.x4.shared.b16 {%0,%1,%2,%3}, [%4];"
                 : "=r"(a0), "=r"(a1), "=r"(a2), "=r"(a3) : "r"(addr));
}
__device__ __forceinline__ void ldsm_x2(uint32_t& b0, uint32_t& b1, uint32_t addr) {
    asm volatile("ldmatrix.sync.aligned.m8n8.x2.shared.b16 {%0,%1}, [%2];"
                 : "=r"(b0), "=r"(b1) : "r"(addr));
}
__device__ __forceinline__ void mma16816(float* d, uint32_t a0, uint32_t a1,
                                         uint32_t a2, uint32_t a3,
                                         uint32_t b0, uint32_t b1) {
    asm volatile("mma.sync.aligned.m16n8k16.row.col.f32.bf16.bf16.f32 "
                 "{%0,%1,%2,%3},{%4,%5,%6,%7},{%8,%9},{%0,%1,%2,%3};"
                 : "+f"(d[0]), "+f"(d[1]), "+f"(d[2]), "+f"(d[3])
                 : "r"(a0), "r"(a1), "r"(a2), "r"(a3), "r"(b0), "r"(b1));
}

// ---------------- GEMM over one tap ----------------------------------------
// d[mi][nf] += data[l + rshift][k] * W[f][k];  l = wl*32+mi*16+rows, f = wf*56+nf*8+cols
// sData: [130][120] bf16, row stride 240B. W: [112][120] bf16, row stride 240B.
__device__ __forceinline__ void gemm_tap(uint32_t sData_u, uint32_t wb_u,
                                         float (&d)[2][7][4], int rshift,
                                         int lane, int wf, int wl) {
    const int lam = lane & 15;
#pragma unroll
    for (int ks = 0; ks < 7; ks++) {
        uint32_t b0[7], b1[7];
#pragma unroll
        for (int nf = 0; nf < 7; nf++) {
            uint32_t addr = wb_u + (uint32_t)(wf * 56 + nf * 8 + (lam & 7)) * 240
                          + ks * 32 + ((lam >> 3) & 1) * 16;
            ldsm_x2(b0[nf], b1[nf], addr);
        }
#pragma unroll
        for (int mi = 0; mi < 2; mi++) {
            uint32_t addr = sData_u + (uint32_t)(wl * 32 + mi * 16 + rshift + lam) * 240
                          + ks * 32 + (lane >> 4) * 16;
            uint32_t a0, a1, a2, a3;
            ldsm_x4(a0, a1, a2, a3, addr);
#pragma unroll
            for (int nf = 0; nf < 7; nf++)
                mma16816(d[mi][nf], a0, a1, a2, a3, b0[nf], b1[nf]);
        }
    }
}

// ---------------- KC1: emb gather + conv1 -> h1 + hmean partials -----------
// smem: data [130][120]bf16 @0 (31200) | sW 3x112x120 @31200 (80640)
// | bias @111840 (512) | hsum @112352 (448) => 112800 B (2 CTAs/SM)
#define C1_W    31200
#define C1_BIAS 111840
#define C1_HS   112352
#define C1_SMEM 112800
__global__ __launch_bounds__(256, 2) void kC1(const int* __restrict__ x,
                                              const float* __restrict__ emb,
                                              const float* __restrict__ b1) {
    extern __shared__ char sm[];
    uint32_t* sD32 = (uint32_t*)sm;
    float* sBias = (float*)(sm + C1_BIAS);
    float* sHs = (float*)(sm + C1_HS);
    const int cx = blockIdx.x, b = blockIdx.y, tid = threadIdx.x;
    const int lane = tid & 31, wid = tid >> 5, wf = wid & 1, wl = wid >> 1;
    const int l0 = cx * 128;
    const int* xb = x + b * L_;
    const float2* e2 = (const float2*)emb;

    const uint4* ws = (const uint4*)g_Wb1;
    for (int i = tid; i < 5040; i += 256) {
        int t = i / 1680, r = i - t * 1680;
        ((uint4*)(sm + C1_W))[t * 1680 + r] = ws[t * 1920 + r];
    }
    for (int idx = tid; idx < 130 * 60; idx += 256) {
        int r = idx / 60, cpr = idx - r * 60;
        int l = l0 - 1 + r;
        uint32_t pk = 0;
        if ((unsigned)l < (unsigned)L_ && cpr < 50) {
            int tok = xb[l];
            float2 v = e2[tok * 50 + cpr];
            __nv_bfloat162 bp = __floats2bfloat162_rn(v.x, v.y);
            pk = *(uint32_t*)&bp;
        }
        sD32[r * 60 + cpr] = pk;
    }
    if (tid < 128) sBias[tid] = (tid < 100) ? b1[tid] : 0.f;
    if (tid < 112) sHs[tid] = 0.f;
    __syncthreads();

    const uint32_t sData_u = smem_u32(sm), sW_u = sData_u + C1_W;
    float d[2][7][4];
#pragma unroll
    for (int mi = 0; mi < 2; mi++)
#pragma unroll
        for (int nf = 0; nf < 7; nf++)
#pragma unroll
            for (int q = 0; q < 4; q++) d[mi][nf][q] = 0.f;
    gemm_tap(sData_u, sW_u, d, 0, lane, wf, wl);
    gemm_tap(sData_u, sW_u + 26880, d, 1, lane, wf, wl);
    gemm_tap(sData_u, sW_u + 53760, d, 2, lane, wf, wl);

    const int lq = lane >> 2, fq = lane & 3;
    uint32_t* dst = g_h1 + ((size_t)b * L_ + l0) * 56;
    float acc[7][2];
#pragma unroll
    for (int nf = 0; nf < 7; nf++) { acc[nf][0] = 0.f; acc[nf][1] = 0.f; }
#pragma unroll
    for (int mi = 0; mi < 2; mi++) {
        int lr = wl * 32 + mi * 16 + lq;
#pragma unroll
        for (int nf = 0; nf < 7; nf++) {
            int fp = wf * 28 + nf * 4 + fq;
            float bx = sBias[2 * fp], by = sBias[2 * fp + 1];
            float v0 = fmaxf(d[mi][nf][0] + bx, 0.f), v1 = fmaxf(d[mi][nf][1] + by, 0.f);
            float v2 = fmaxf(d[mi][nf][2] + bx, 0.f), v3 = fmaxf(d[mi][nf][3] + by, 0.f);
            __nv_bfloat162 p0 = __floats2bfloat162_rn(v0, v1);
            __nv_bfloat162 p1 = __floats2bfloat162_rn(v2, v3);
            dst[(size_t)lr * 56 + fp] = *(uint32_t*)&p0;
            dst[(size_t)(lr + 8) * 56 + fp] = *(uint32_t*)&p1;
            acc[nf][0] += v0 + v2;
            acc[nf][1] += v1 + v3;
        }
    }
#pragma unroll
    for (int nf = 0; nf < 7; nf++)
#pragma unroll
        for (int j = 0; j < 2; j++) {
            float v = acc[nf][j];
            v += __shfl_xor_sync(0xffffffffu, v, 4);
            v += __shfl_xor_sync(0xffffffffu, v, 8);
            v += __shfl_xor_sync(0xffffffffu, v, 16);
            if (lane < 4) atomicAdd(&sHs[wf * 56 + nf * 8 + fq * 2 + j], v);
        }
    __syncthreads();
    if (tid < 112) g_hpart[(b * 4 + cx) * 128 + tid] = sHs[tid];
}

// ---------------- KG: hmean -> g -> gz -------------------------------------
__global__ __launch_bounds__(128) void kG(const float* __restrict__ giw,
                                          const float* __restrict__ gib,
                                          const float* __restrict__ c3w,
                                          const float* __restrict__ c3b) {
    const int b = blockIdx.x, tid = threadIdx.x;
    __shared__ float shm[100], sg[100];
    if (tid < 100) {
        const float* p = g_hpart + b * 4 * 128 + tid;
        shm[tid] = (p[0] + p[128] + p[256] + p[384]) * (1.f / (float)L_);
    }
    __syncthreads();
    if (tid < 100) {
        float a = gib[tid];
        const float* wr = &giw[tid * 100];
        for (int f = 0; f < 100; f++) a = fmaf(wr[f], shm[f], a);
        sg[tid] = fmaxf(a, 0.f);
    }
    __syncthreads();
    if (tid < 100) {
        float a = c3b[tid];
        const float* wr = &c3w[tid * 200];
        for (int h = 0; h < 100; h++) a = fmaf(wr[h], sg[h], a);
        g_gz[b * 128 + tid] = a;
    }
}

// ---------------- KC2: conv2 (h1 -> h2) ------------------------------------
#define C2_W    31200
#define C2_BIAS 111840
#define C2_SMEM 112352
__global__ __launch_bounds__(256, 2) void kC2(const float* __restrict__ b2) {
    extern __shared__ char sm[];
    float* sBias = (float*)(sm + C2_BIAS);
    const int cx = blockIdx.x, b = blockIdx.y, tid = threadIdx.x;
    const int lane = tid & 31, wid = tid >> 5, wf = wid & 1, wl = wid >> 1;
    const int l0 = cx * 128;
    const uint4* src = (const uint4*)(g_h1 + (size_t)b * L_ * 56);

    const uint4* ws = (const uint4*)g_Wb2;
    for (int i = tid; i < 5040; i += 256) {
        int t = i / 1680, r = i - t * 1680;
        ((uint4*)(sm + C2_W))[t * 1680 + r] = ws[t * 1920 + r];
    }
    for (int idx = tid; idx < 130 * 15; idx += 256) {
        int r = idx / 15, q = idx - r * 15;
        int l = l0 - 1 + r;
        uint4 v = make_uint4(0, 0, 0, 0);
        if (q < 14 && (unsigned)l < (unsigned)L_) v = src[l * 14 + q];
        ((uint4*)sm)[r * 15 + q] = v;
    }
    if (tid < 128) sBias[tid] = (tid < 100) ? b2[tid] : 0.f;
    __syncthreads();

    const uint32_t sData_u = smem_u32(sm), sW_u = sData_u + C2_W;
    float d[2][7][4];
#pragma unroll
    for (int mi = 0; mi < 2; mi++)
#pragma unroll
        for (int nf = 0; nf < 7; nf++)
#pragma unroll
            for (int q = 0; q < 4; q++) d[mi][nf][q] = 0.f;
    gemm_tap(sData_u, sW_u, d, 0, lane, wf, wl);
    gemm_tap(sData_u, sW_u + 26880, d, 1, lane, wf, wl);
    gemm_tap(sData_u, sW_u + 53760, d, 2, lane, wf, wl);

    const int lq = lane >> 2, fq = lane & 3;
    uint32_t* dst = g_h2 + ((size_t)b * L_ + l0) * 56;
#pragma unroll
    for (int mi = 0; mi < 2; mi++) {
        int lr = wl * 32 + mi * 16 + lq;
#pragma unroll
        for (int nf = 0; nf < 7; nf++) {
            int fp = wf * 28 + nf * 4 + fq;
            float bx = sBias[2 * fp], by = sBias[2 * fp + 1];
            float v0 = fmaxf(d[mi][nf][0] + bx, 0.f), v1 = fmaxf(d[mi][nf][1] + by, 0.f);
            float v2 = fmaxf(d[mi][nf][2] + bx, 0.f), v3 = fmaxf(d[mi][nf][3] + by, 0.f);
            __nv_bfloat162 p0 = __floats2bfloat162_rn(v0, v1);
            __nv_bfloat162 p1 = __floats2bfloat162_rn(v2, v3);
            dst[(size_t)lr * 56 + fp] = *(uint32_t*)&p0;
            dst[(size_t)(lr + 8) * 56 + fp] = *(uint32_t*)&p1;
        }
    }
}

// ---------------- KC3: li conv -> conv3(loc)+gz -> conv4 -> logits ---------
// smem: data @0 (31200) | wslot @31200 (26880) | bias @58080 | gz @58592
// | c4 @59104 | sLog @59616 (512) => 60128 B
#define C3_W    31200
#define C3_BIAS 58080
#define C3_GZ   58592
#define C3_C4   59104
#define C3_LOG  59616
#define C3_SMEM 60128
__global__ __launch_bounds__(256, 2) void kC3(const float* __restrict__ lb,
                                              const float* __restrict__ c4w,
                                              const float* __restrict__ c4b) {
    extern __shared__ char sm[];
    uint32_t* sD32 = (uint32_t*)sm;
    float* sBias = (float*)(sm + C3_BIAS);
    float* sGz = (float*)(sm + C3_GZ);
    float* sC4 = (float*)(sm + C3_C4);
    float* sLog = (float*)(sm + C3_LOG);
    const int cx = blockIdx.x, b = blockIdx.y, tid = threadIdx.x;
    const int lane = tid & 31, wid = tid >> 5, wf = wid & 1, wl = wid >> 1;
    const int l0 = cx * 128;
    const uint4* src = (const uint4*)(g_h2 + (size_t)b * L_ * 56);

    for (int idx = tid; idx < 130 * 15; idx += 256) {
        int r = idx / 15, q = idx - r * 15;
        int l = l0 - 1 + r;
        uint4 v = make_uint4(0, 0, 0, 0);
        if (q < 14 && (unsigned)l < (unsigned)L_) v = src[l * 14 + q];
        ((uint4*)sm)[r * 15 + q] = v;
    }
    if (tid < 128) {
        sBias[tid] = (tid < 100) ? lb[tid] : 0.f;
        sGz[tid] = (tid < 100) ? g_gz[b * 128 + tid] : 0.f;
        sC4[tid] = (tid < 100) ? c4w[tid] : 0.f;
        sLog[tid] = 0.f;
    }

    const uint32_t sData_u = smem_u32(sm), wslot_u = sData_u + C3_W;
    uint4* wslot4 = (uint4*)(sm + C3_W);
    const uint4* wsL = (const uint4*)g_WbL;

    float d[2][7][4];
#pragma unroll
    for (int mi = 0; mi < 2; mi++)
#pragma unroll
        for (int nf = 0; nf < 7; nf++)
#pragma unroll
            for (int q = 0; q < 4; q++) d[mi][nf][q] = 0.f;

    for (int t = 0; t < 3; t++) {
        __syncthreads();                 // previous gemm/store done with wslot
        for (int i = tid; i < 1680; i += 256) wslot4[i] = wsL[t * 1920 + i];
        __syncthreads();
        gemm_tap(sData_u, wslot_u, d, t, lane, wf, wl);
    }
    __syncthreads();                     // li gemm done (sData reads complete)

    // Loc = relu(D + lb) -> packed bf16 into sData rows 0..127; stage W3
    const int lq = lane >> 2, fq = lane & 3;
#pragma unroll
    for (int mi = 0; mi < 2; mi++) {
        int lr = wl * 32 + mi * 16 + lq;
#pragma unroll
        for (int nf = 0; nf < 7; nf++) {
            int fp = wf * 28 + nf * 4 + fq;
            float bx = sBias[2 * fp], by = sBias[2 * fp + 1];
            float v0 = fmaxf(d[mi][nf][0] + bx, 0.f), v1 = fmaxf(d[mi][nf][1] + by, 0.f);
            float v2 = fmaxf(d[mi][nf][2] + bx, 0.f), v3 = fmaxf(d[mi][nf][3] + by, 0.f);
            __nv_bfloat162 p0 = __floats2bfloat162_rn(v0, v1);
            __nv_bfloat162 p1 = __floats2bfloat162_rn(v2, v3);
            sD32[lr * 60 + fp] = *(uint32_t*)&p0;
            sD32[(lr + 8) * 60 + fp] = *(uint32_t*)&p1;
        }
    }
    const uint4* ws3 = (const uint4*)g_Wb3;
    for (int i = tid; i < 1680; i += 256) wslot4[i] = ws3[i];
    __syncthreads();

    float d2[2][7][4];
#pragma unroll
    for (int mi = 0; mi < 2; mi++)
#pragma unroll
        for (int nf = 0; nf < 7; nf++)
#pragma unroll
            for (int q = 0; q < 4; q++) d2[mi][nf][q] = 0.f;
    gemm_tap(sData_u, wslot_u, d2, 0, lane, wf, wl);

    // logits: sum_f c4[f]*relu(D2 + gz[f])
#pragma unroll
    for (int mi = 0; mi < 2; mi++) {
        int lr = wl * 32 + mi * 16 + lq;
        float pA = 0.f, pB = 0.f;
#pragma unroll
        for (int nf = 0; nf < 7; nf++) {
            int f0 = wf * 56 + nf * 8 + fq * 2;
            float g0 = sGz[f0], g1 = sGz[f0 + 1];
            float c0 = sC4[f0], c1 = sC4[f0 + 1];
            pA += c0 * fmaxf(d2[mi][nf][0] + g0, 0.f) + c1 * fmaxf(d2[mi][nf][1] + g1, 0.f);
            pB += c0 * fmaxf(d2[mi][nf][2] + g0, 0.f) + c1 * fmaxf(d2[mi][nf][3] + g1, 0.f);
        }
        pA += __shfl_xor_sync(0xffffffffu, pA, 1);
        pA += __shfl_xor_sync(0xffffffffu, pA, 2);
        pB += __shfl_xor_sync(0xffffffffu, pB, 1);
        pB += __shfl_xor_sync(0xffffffffu, pB, 2);
        if (fq == 0) {
            atomicAdd(&sLog[lr], pA);
            atomicAdd(&sLog[lr + 8], pB);
        }
    }
    __syncthreads();
    if (tid < 128) g_logits[b * L_ + l0 + tid] = sLog[tid] + c4b[0];
}

// ---------------- reductions -----------------------------------------------
__device__ __forceinline__ float bmax256(float v, float* sred) {
#pragma unroll
    for (int o = 16; o > 0; o >>= 1) v = fmaxf(v, __shfl_xor_sync(0xffffffffu, v, o));
    int w = threadIdx.x >> 5;
    if ((threadIdx.x & 31) == 0) sred[w] = v;
    __syncthreads();
    if (threadIdx.x == 0) {
        float t = sred[0];
#pragma unroll
        for (int i = 1; i < 8; i++) t = fmaxf(t, sred[i]);
        sred[0] = t;
    }
    __syncthreads();
    float r = sred[0];
    __syncthreads();
    return r;
}
__device__ __forceinline__ float bsum256(float v, float* sred) {
#pragma unroll
    for (int o = 16; o > 0; o >>= 1) v += __shfl_xor_sync(0xffffffffu, v, o);
    int w = threadIdx.x >> 5;
    if ((threadIdx.x & 31) == 0) sred[w] = v;
    __syncthreads();
    if (threadIdx.x == 0) {
        float t = sred[0];
#pragma unroll
        for (int i = 1; i < 8; i++) t += sred[i];
        sred[0] = t;
    }
    __syncthreads();
    float r = sred[0];
    __syncthreads();
    return r;
}

// ---------------- K4: gumbel softmax over L, max over K --------------------
__global__ __launch_bounds__(256) void k4_init(float* __restrict__ cs) {
    int i = blockIdx.x * 256 + threadIdx.x;
    if (i < B_ * L_) cs[i] = 0.f;
}
__global__ __launch_bounds__(256) void k4_gumbel(const float* __restrict__ u,
                                                 float* __restrict__ cs_out) {
    const int k = blockIdx.x, b = blockIdx.y, tid = threadIdx.x;
    __shared__ float sred[8];
    const float EPS = 1.1920929e-07f;
    const float invT = 1.0f / 0.3f;
    const float* lg = g_logits + b * L_;
    const float* ub = u + (b * KK_ + k) * L_;
    float u0 = ub[tid], u1 = ub[tid + 256];
    u0 = fminf(fmaxf(u0, EPS), 1.0f - EPS);
    u1 = fminf(fmaxf(u1, EPS), 1.0f - EPS);
    float nv0 = (-logf(-logf(u0)) + lg[tid]) * invT;
    float nv1 = (-logf(-logf(u1)) + lg[tid + 256]) * invT;
    float m = bmax256(fmaxf(nv0, nv1), sred);
    float e0 = expf(nv0 - m), e1 = expf(nv1 - m);
    float s = bsum256(e0 + e1, sred);
    float rs = 1.f / s;
    atomicMax((int*)&cs_out[b * L_ + tid], __float_as_int(e0 * rs));
    atomicMax((int*)&cs_out[b * L_ + tid + 256], __float_as_int(e1 * rs));
}

// ---------------- K5: weighted pooling + MLP + sigmoid ---------------------
__global__ __launch_bounds__(128) void k5_final(const int* __restrict__ x,
                                                const float* __restrict__ emb,
                                                const float* __restrict__ f1w,
                                                const float* __restrict__ f1b,
                                                const float* __restrict__ hw,
                                                const float* __restrict__ hb,
                                                const float* __restrict__ cs,
                                                float* __restrict__ out) {
    const int b = blockIdx.x, tid = threadIdx.x;
    __shared__ float scs[L_];
    __shared__ int sx[L_];
    __shared__ float spool[100];
    __shared__ float sh[100];
    __shared__ float sred[4];
    for (int l = tid; l < L_; l += 128) {
        scs[l] = cs[b * L_ + l];
        sx[l] = x[b * L_ + l];
    }
    __syncthreads();
    if (tid < 100) {
        float acc = 0.f;
        for (int l = 0; l < L_; l += 8) {
            float p[8];
#pragma unroll
            for (int q = 0; q < 8; q++) p[q] = emb[sx[l + q] * 100 + tid];
#pragma unroll
            for (int q = 0; q < 8; q++) acc = fmaf(scs[l + q], p[q], acc);
        }
        spool[tid] = acc * (1.f / (float)L_);
    }
    __syncthreads();
    if (tid < 100) {
        float a = f1b[tid];
        const float* wr = &f1w[tid * 100];
        for (int e = 0; e < 100; e++) a = fmaf(wr[e], spool[e], a);
        sh[tid] = fmaxf(a, 0.f);
    }
    __syncthreads();
    float hv = (tid < 100) ? hw[tid] * sh[tid] : 0.f;
#pragma unroll
    for (int o = 16; o > 0; o >>= 1) hv += __shfl_xor_sync(0xffffffffu, hv, o);
    if ((tid & 31) == 0) sred[tid >> 5] = hv;
    __syncthreads();
    if (tid == 0) {
        float t = sred[0] + sred[1] + sred[2] + sred[3] + hb[0];
        out[b] = 1.f / (1.f + expf(-t));
    }
}

// ---------------- launch ----------------------------------------------------
extern "C" void kernel_launch(void* const* d_in, const int* in_sizes, int n_in,
                              void* d_out, int out_size) {
    const int*   x   = (const int*)  d_in[0];
    const float* u   = (const float*)d_in[1];
    const float* emb = (const float*)d_in[2];
    const float* c1w = (const float*)d_in[3];
    const float* c1b = (const float*)d_in[4];
    const float* giw = (const float*)d_in[5];
    const float* gib = (const float*)d_in[6];
    const float* c2w = (const float*)d_in[7];
    const float* c2b = (const float*)d_in[8];
    const float* liw = (const float*)d_in[9];
    const float* lib = (const float*)d_in[10];
    const float* c3w = (const float*)d_in[11];
    const float* c3b = (const float*)d_in[12];
    const float* c4w = (const float*)d_in[13];
    const float* c4b = (const float*)d_in[14];
    const float* f1w = (const float*)d_in[15];
    const float* f1b = (const float*)d_in[16];
    const float* hw  = (const float*)d_in[17];
    const float* hb  = (const float*)d_in[18];

    float* out = (float*)d_out;          // [B,1] first
    float* cs  = out + B_;               // then csamples [B,L]

    cudaFuncSetAttribute(kC1, cudaFuncAttributeMaxDynamicSharedMemorySize, C1_SMEM);
    cudaFuncSetAttribute(kC2, cudaFuncAttributeMaxDynamicSharedMemorySize, C2_SMEM);
    cudaFuncSetAttribute(kC3, cudaFuncAttributeMaxDynamicSharedMemorySize, C3_SMEM);

    k0_prep<<<593, 256>>>(c1w, c2w, liw, c3w);
    kC1<<<dim3(4, B_), 256, C1_SMEM>>>(x, emb, c1b);
    kG<<<B_, 128>>>(giw, gib, c3w, c3b);
    kC2<<<dim3(4, B_), 256, C2_SMEM>>>(c2b);
    kC3<<<dim3(4, B_), 256, C3_SMEM>>>(lib, c4w, c4b);
    k4_init<<<(B_ * L_ + 255) / 256, 256>>>(cs);
    k4_gumbel<<<dim3(KK_, B_), 256>>>(u, cs);
    k5_final<<<B_, 128>>>(x, emb, f1w, f1b, hw, hb, cs, out);
}